// round 1
// baseline (speedup 1.0000x reference)
#include <cuda_runtime.h>
#include <math.h>

// Problem constants
#define BQ 4
#define MQ 2048
#define KQ 64
#define CQ 64
#define SRQ 16
#define SQ 64          // NSEG * SAMPLE_RATE
#define PPQ 28         // params per primitive
#define MTILE 64
#define NTHREADS 256

// Output layout (tuple flattened in order):
// occupancies (B,M) | primitive_sdf (B,M,K) | inter (B,M,C) | support (B,M,K)
#define OUT_OCC   0
#define OUT_SDF   (BQ*MQ)                       // 8192
#define OUT_INTER (OUT_SDF + BQ*MQ*KQ)          // 532480
#define OUT_SUP   (OUT_INTER + BQ*MQ*CQ)        // 1056768

// Shared memory layout (float offsets)
#define OFF_CURVE 0                      // 64 * 65 float2 = 8320 floats (ring-duplicated)
#define OFF_PRIM  (64*65*2)              // 8320  : 64 * 8 floats
#define OFF_W     (OFF_PRIM + 512)       // 8832  : 64*64
#define OFF_U     (OFF_W + 4096)         // 12928 : 64
#define OFF_OCC   (OFF_U + 64)           // 12992 : 64*65 (pitch 65, conflict-free)
#define OFF_SDF   (OFF_OCC + 4160)       // 17152 : 64*65 (reused for inter)
#define OFF_DMIN  (OFF_SDF + 4160)       // 21312 : 64*65
#define SMEM_FLOATS (OFF_DMIN + 4160)    // 25472 floats = 101888 B

__global__ __launch_bounds__(NTHREADS, 1)
void extrude_kernel(const float* __restrict__ pts,   // (B,M,3)
                    const float* __restrict__ prim,  // (B,28,K)
                    const float* __restrict__ Wg,    // (B,K,C)
                    const float* __restrict__ Ug,    // (B,C)
                    const int*   __restrict__ flag,  // is_training (may be null)
                    float* __restrict__ out)
{
    extern __shared__ float sm[];
    float2* curve  = (float2*)(sm + OFF_CURVE);   // [k][s], pitch 65, cv[64]=cv[0]
    float*  prim_s = sm + OFF_PRIM;               // per-k: qw,qx,qy,qz,tx,ty,tz,|h|
    float*  W_s    = sm + OFF_W;
    float*  u_s    = sm + OFF_U;
    float*  occ_s  = sm + OFF_OCC;
    float*  sdf_s  = sm + OFF_SDF;
    float*  dmin_s = sm + OFF_DMIN;

    const int tid = threadIdx.x;
    const int b   = blockIdx.y;
    const int m0  = blockIdx.x * MTILE;

    const float* P = prim + b * PPQ * KQ;

    // ---- Phase 0: per-b primitive params, weights, rational-bezier curve ----
    if (tid < KQ) {
        const int k = tid;
        float q0 = P[0*KQ+k], q1 = P[1*KQ+k], q2 = P[2*KQ+k], q3 = P[3*KQ+k];
        float inv = rsqrtf(q0*q0 + q1*q1 + q2*q2 + q3*q3 + 1e-8f);
        prim_s[k*8+0] =  q0*inv;     // w of normalized quaternion
        prim_s[k*8+1] = -q1*inv;     // qv = -qn[1:4]
        prim_s[k*8+2] = -q2*inv;
        prim_s[k*8+3] = -q3*inv;
        prim_s[k*8+4] = P[4*KQ+k];
        prim_s[k*8+5] = P[5*KQ+k];
        prim_s[k*8+6] = P[6*KQ+k];
        prim_s[k*8+7] = fabsf(P[7*KQ+k]);
    }
    for (int i = tid; i < KQ*CQ; i += NTHREADS) W_s[i] = Wg[b*KQ*CQ + i];
    if (tid < CQ) u_s[tid] = Ug[b*CQ + tid];

    {   // one (k, seg) pair per thread: 64*4 = 256
        const int k   = tid >> 2;
        const int seg = tid & 3;
        const double PI = 3.14159265358979323846;
        const double thetaD = 2.0*PI/16.0 + atan(tan(2.0*PI/16.0)/3.0);
        const int sn = (seg + 1) & 3;
        const float a0  = (float)(PI/2.0 * seg);
        const float a1  = (float)(PI/2.0 * seg + thetaD);
        const float a2  = (float)(PI/2.0 * (seg+1) - thetaD);
        const float a0n = (float)(PI/2.0 * sn);
        const float r0 = fabsf(P[(8 + seg*3 + 0)*KQ + k]);
        const float r1 = fabsf(P[(8 + seg*3 + 1)*KQ + k]);
        const float r2 = fabsf(P[(8 + seg*3 + 2)*KQ + k]);
        const float rn = fabsf(P[(8 + sn*3  + 0)*KQ + k]);
        const float w1 = fabsf(P[(20 + seg*2 + 0)*KQ + k]);
        const float w2 = fabsf(P[(20 + seg*2 + 1)*KQ + k]);
        const float P0x = cosf(a0)*r0,  P0y = sinf(a0)*r0;
        const float P1x = cosf(a1)*r1,  P1y = sinf(a1)*r1;
        const float P2x = cosf(a2)*r2,  P2y = sinf(a2)*r2;
        const float P3x = cosf(a0n)*rn, P3y = sinf(a0n)*rn;
        float2* cv = curve + k*65 + seg*SRQ;
        #pragma unroll
        for (int j = 0; j < SRQ; j++) {
            float t  = j * (1.0f/SRQ);
            float u1 = 1.0f - t;
            float b0 = u1*u1*u1;
            float b1 = 3.0f*u1*u1*t;
            float b2 = 3.0f*u1*t*t;
            float b3 = t*t*t;
            float wb1 = w1*b1, wb2 = w2*b2;
            float invd = 1.0f / (b0 + wb1 + wb2 + b3);
            float x = (P0x*b0 + P1x*wb1 + P2x*wb2 + P3x*b3) * invd;
            float y = (P0y*b0 + P1y*wb1 + P2y*wb2 + P3y*b3) * invd;
            cv[j] = make_float2(x, y);
            if (seg == 0 && j == 0) curve[k*65 + 64] = make_float2(x, y); // close ring
        }
    }
    __syncthreads();

    // ---- Phase A: per-(m,k) SDF. tid -> (m_local = tid&63, ks = tid>>6 handles 16 k) ----
    const int m_local = tid & 63;
    const int ks      = tid >> 6;
    const int gm      = b*MQ + m0 + m_local;
    const float px = pts[gm*3+0], py = pts[gm*3+1], pz = pts[gm*3+2];

    for (int i = 0; i < 16; i++) {
        const int k = ks*16 + i;
        const float* pr = prim_s + k*8;   // warp-uniform -> broadcast
        const float qw = pr[0], qx = pr[1], qy = pr[2], qz = pr[3];
        const float ax = px - pr[4], ay = py - pr[5], az = pz - pr[6];
        const float h  = pr[7];
        // rotate: pl = a + w*t2 + cross(qv, t2), t2 = 2*cross(qv, a)
        const float t2x = 2.0f*(qy*az - qz*ay);
        const float t2y = 2.0f*(qz*ax - qx*az);
        const float t2z = 2.0f*(qx*ay - qy*ax);
        const float plx = ax + qw*t2x + (qy*t2z - qz*t2y);
        const float ply = ay + qw*t2y + (qz*t2x - qx*t2z);
        const float plz = az + qw*t2z + (qx*t2y - qy*t2x);

        const float2* cv = curve + k*65;
        float2 c0 = cv[0];
        float rx = c0.x - plx, ry = c0.y - ply;
        float d2min = rx*rx + ry*ry;
        int wind = 0;
        #pragma unroll 8
        for (int s = 0; s < SQ; s++) {
            float2 c1 = cv[s+1];                 // ring-closed, no wrap branch
            float nx = c1.x - plx, ny = c1.y - ply;
            float cr = rx*ny - ry*nx;
            float d2 = nx*nx + ny*ny;
            d2min = fminf(d2min, d2);            // s=63 re-mins rel0: harmless
            bool up   = (ry <= 0.0f) && (ny >  0.0f);
            bool down = (ry >  0.0f) && (ny <= 0.0f);
            if (up   && cr > 0.0f) wind++;       // exact integer winding number
            if (down && cr < 0.0f) wind--;
            rx = nx; ry = ny;
        }
        const float dmin  = sqrtf(d2min + 1e-12f);
        const float sdf2d = (wind != 0) ? -dmin : dmin;
        const float dz = fabsf(plz) - h;
        const float e1 = fmaxf(sdf2d, 0.0f), e2 = fmaxf(dz, 0.0f);
        const float sdf = fminf(fmaxf(sdf2d, dz), 0.0f)
                        + sqrtf(e1*e1 + e2*e2 + 1e-12f);
        const float ex  = __expf(fminf(150.0f*sdf, 80.0f));
        const float occ = __fdividef(1.0f, 1.0f + ex);   // sigmoid(-150*sdf)
        sdf_s [k*65 + m_local] = sdf;
        dmin_s[k*65 + m_local] = dmin;
        occ_s [k*65 + m_local] = occ;
    }
    __syncthreads();

    // ---- Flush sdf / dmin coalesced ----
    const int outbase = (b*MQ + m0) * KQ;
    for (int idx = tid; idx < MTILE*KQ; idx += NTHREADS) {
        const int mm = idx >> 6, kk = idx & 63;
        out[OUT_SDF + outbase + idx] = sdf_s [kk*65 + mm];
        out[OUT_SUP + outbase + idx] = dmin_s[kk*65 + mm];
    }
    __syncthreads();   // sdf_s about to be reused for inter

    // ---- Phase B: intersection layer. tid -> (m_local, cs = tid>>6 handles 16 c) ----
    const int training = flag ? *flag : 1;
    for (int j = 0; j < 16; j++) {
        const int c = ks*16 + j;
        float se = 0.0f, sp = 0.0f, mn = 3.0e38f;
        #pragma unroll 8
        for (int k = 0; k < KQ; k++) {
            float o  = occ_s[k*65 + m_local];        // conflict-free
            float wv = W_s[k*64 + c];                // warp-uniform broadcast
            float pre = fmaf(wv, o, 1.0f - wv);      // 1 - wv*(1-o)
            float e = __expf(-40.0f * pre);
            se += e;
            sp  = fmaf(e, pre, sp);
            mn  = fminf(mn, pre);
        }
        float inter = training ? __fdividef(sp, se) : mn;
        sdf_s[c*65 + m_local] = inter;               // reuse buffer
    }
    __syncthreads();

    for (int idx = tid; idx < MTILE*CQ; idx += NTHREADS) {
        const int mm = idx >> 6, cc = idx & 63;
        out[OUT_INTER + outbase + idx] = sdf_s[cc*65 + mm];
    }

    // ---- Phase C: union layer, one thread per point ----
    if (tid < MTILE) {
        const int mm = tid;
        float mx = -3.0e38f;
        #pragma unroll 8
        for (int c = 0; c < CQ; c++) {
            float v = u_s[c] * sdf_s[c*65 + mm];
            mx = fmaxf(mx, v);
        }
        float se = 0.0f, sp = 0.0f;
        #pragma unroll 8
        for (int c = 0; c < CQ; c++) {
            float v = u_s[c] * sdf_s[c*65 + mm];
            float e = __expf(40.0f * (v - mx));
            se += e;
            sp  = fmaf(e, v, sp);
        }
        out[OUT_OCC + b*MQ + m0 + mm] = training ? __fdividef(sp, se) : mx;
    }
}

extern "C" void kernel_launch(void* const* d_in, const int* in_sizes, int n_in,
                              void* d_out, int out_size) {
    const float* pts  = (const float*)d_in[0];
    const float* prim = (const float*)d_in[1];
    const float* Wg   = (const float*)d_in[2];
    const float* Ug   = (const float*)d_in[3];
    const int*   flag = (n_in >= 5) ? (const int*)d_in[4] : nullptr;
    float* out = (float*)d_out;

    const size_t smem = SMEM_FLOATS * sizeof(float);
    cudaFuncSetAttribute(extrude_kernel,
                         cudaFuncAttributeMaxDynamicSharedMemorySize, (int)smem);
    dim3 grid(MQ / MTILE, BQ);      // 32 x 4 = 128 blocks
    extrude_kernel<<<grid, NTHREADS, smem>>>(pts, prim, Wg, Ug, flag, out);
}

// round 2
// speedup vs baseline: 1.1647x; 1.1647x over previous
#include <cuda_runtime.h>
#include <math.h>

// Problem constants
#define BQ 4
#define MQ 2048
#define KQ 64
#define CQ 64
#define SRQ 16
#define SQ 64          // NSEG * SAMPLE_RATE
#define PPQ 28         // params per primitive
#define MTILE 32
#define NTHREADS 512

// Output layout (tuple flattened in order):
// occupancies (B,M) | primitive_sdf (B,M,K) | inter (B,M,C) | support (B,M,K)
#define OUT_OCC   0
#define OUT_SDF   (BQ*MQ)                       // 8192
#define OUT_INTER (OUT_SDF + BQ*MQ*KQ)          // 532480
#define OUT_SUP   (OUT_INTER + BQ*MQ*CQ)        // 1056768

// Shared memory layout (float offsets)
#define OFF_CURVE 0                       // 64 k * 64 s * float2 = 8192 floats (16B-aligned rows)
#define OFF_PRIM  (64*64*2)               // 8192  : 64 * 8
#define OFF_W     (OFF_PRIM + 512)        // 8704  : 64*64
#define OFF_U     (OFF_W + 4096)          // 12800 : 64
#define OFF_OCC   (OFF_U + 64)            // 12864 : 64*33 (pitch 33, conflict-free)
#define OFF_SDF   (OFF_OCC + 64*33)       // 14976 : 64*33 (reused for inter)
#define OFF_DMIN  (OFF_SDF + 64*33)       // 17088 : 64*33
#define SMEM_FLOATS (OFF_DMIN + 64*33)    // 19200 floats = 76800 B  -> 2 blocks/SM

// winding edge update: edge from rel (rx,ry) to next (nx,ny)
#define EDGE_STEP(rx, ry, nx, ny)                                   \
    {                                                               \
        float cr = (rx)*(ny) - (ry)*(nx);                           \
        bool up   = ((ry) <= 0.0f) && ((ny) >  0.0f);               \
        bool down = ((ry) >  0.0f) && ((ny) <= 0.0f);               \
        if (up   && cr > 0.0f) wind++;                              \
        if (down && cr < 0.0f) wind--;                              \
    }

__global__ __launch_bounds__(NTHREADS, 2)
void extrude_kernel(const float* __restrict__ pts,   // (B,M,3)
                    const float* __restrict__ prim,  // (B,28,K)
                    const float* __restrict__ Wg,    // (B,K,C)
                    const float* __restrict__ Ug,    // (B,C)
                    const int*   __restrict__ flag,  // is_training
                    float* __restrict__ out)
{
    extern __shared__ float sm[];
    float2* curve  = (float2*)(sm + OFF_CURVE);   // [k][s], pitch 64
    float*  prim_s = sm + OFF_PRIM;               // per-k: qw,qx,qy,qz,tx,ty,tz,|h|
    float*  W_s    = sm + OFF_W;
    float*  u_s    = sm + OFF_U;
    float*  occ_s  = sm + OFF_OCC;
    float*  sdf_s  = sm + OFF_SDF;
    float*  dmin_s = sm + OFF_DMIN;

    const int tid = threadIdx.x;
    const int b   = blockIdx.y;
    const int m0  = blockIdx.x * MTILE;

    const float* P = prim + b * PPQ * KQ;

    // ---- Phase 0: per-b primitive params, weights, rational-bezier curve ----
    if (tid < KQ) {
        const int k = tid;
        float q0 = P[0*KQ+k], q1 = P[1*KQ+k], q2 = P[2*KQ+k], q3 = P[3*KQ+k];
        float inv = rsqrtf(q0*q0 + q1*q1 + q2*q2 + q3*q3 + 1e-8f);
        prim_s[k*8+0] =  q0*inv;     // w of normalized quaternion
        prim_s[k*8+1] = -q1*inv;     // qv = -qn[1:4]
        prim_s[k*8+2] = -q2*inv;
        prim_s[k*8+3] = -q3*inv;
        prim_s[k*8+4] = P[4*KQ+k];
        prim_s[k*8+5] = P[5*KQ+k];
        prim_s[k*8+6] = P[6*KQ+k];
        prim_s[k*8+7] = fabsf(P[7*KQ+k]);
    }
    for (int i = tid; i < KQ*CQ; i += NTHREADS) W_s[i] = Wg[b*KQ*CQ + i];
    if (tid >= KQ && tid < KQ + CQ) u_s[tid - KQ] = Ug[b*CQ + tid - KQ];

    if (tid < 256) {   // one (k, seg) pair per thread: 64*4 = 256
        const int k   = tid >> 2;
        const int seg = tid & 3;
        const double PI = 3.14159265358979323846;
        const double thetaD = 2.0*PI/16.0 + atan(tan(2.0*PI/16.0)/3.0);
        const int sn = (seg + 1) & 3;
        const float a0  = (float)(PI/2.0 * seg);
        const float a1  = (float)(PI/2.0 * seg + thetaD);
        const float a2  = (float)(PI/2.0 * (seg+1) - thetaD);
        const float a0n = (float)(PI/2.0 * sn);
        const float r0 = fabsf(P[(8 + seg*3 + 0)*KQ + k]);
        const float r1 = fabsf(P[(8 + seg*3 + 1)*KQ + k]);
        const float r2 = fabsf(P[(8 + seg*3 + 2)*KQ + k]);
        const float rn = fabsf(P[(8 + sn*3  + 0)*KQ + k]);
        const float w1 = fabsf(P[(20 + seg*2 + 0)*KQ + k]);
        const float w2 = fabsf(P[(20 + seg*2 + 1)*KQ + k]);
        const float P0x = cosf(a0)*r0,  P0y = sinf(a0)*r0;
        const float P1x = cosf(a1)*r1,  P1y = sinf(a1)*r1;
        const float P2x = cosf(a2)*r2,  P2y = sinf(a2)*r2;
        const float P3x = cosf(a0n)*rn, P3y = sinf(a0n)*rn;
        float2* cv = curve + k*64 + seg*SRQ;
        #pragma unroll
        for (int j = 0; j < SRQ; j++) {
            float t  = j * (1.0f/SRQ);
            float u1 = 1.0f - t;
            float b0 = u1*u1*u1;
            float b1 = 3.0f*u1*u1*t;
            float b2 = 3.0f*u1*t*t;
            float b3 = t*t*t;
            float wb1 = w1*b1, wb2 = w2*b2;
            float invd = 1.0f / (b0 + wb1 + wb2 + b3);
            float x = (P0x*b0 + P1x*wb1 + P2x*wb2 + P3x*b3) * invd;
            float y = (P0y*b0 + P1y*wb1 + P2y*wb2 + P3y*b3) * invd;
            cv[j] = make_float2(x, y);
        }
    }
    __syncthreads();

    // ---- Phase A: per-(m,k) SDF. lane = m_local, warp-group handles 4 k ----
    const int m_local = tid & 31;
    const int ks      = tid >> 5;          // 0..15
    const int gm      = b*MQ + m0 + m_local;
    const float px = pts[gm*3+0], py = pts[gm*3+1], pz = pts[gm*3+2];

    for (int i = 0; i < 4; i++) {
        const int k = ks*4 + i;
        const float* pr = prim_s + k*8;    // warp-uniform -> broadcast
        const float qw = pr[0], qx = pr[1], qy = pr[2], qz = pr[3];
        const float ax = px - pr[4], ay = py - pr[5], az = pz - pr[6];
        const float h  = pr[7];
        // rotate: pl = a + w*t2 + cross(qv, t2), t2 = 2*cross(qv, a)
        const float t2x = 2.0f*(qy*az - qz*ay);
        const float t2y = 2.0f*(qz*ax - qx*az);
        const float t2z = 2.0f*(qx*ay - qy*ax);
        const float plx = ax + qw*t2x + (qy*t2z - qz*t2y);
        const float ply = ay + qw*t2y + (qz*t2x - qx*t2z);
        const float plz = az + qw*t2z + (qx*t2y - qy*t2x);

        // curve row k, 32 float4 loads = 64 points (warp-uniform broadcast)
        const float4* cvp = (const float4*)(curve + k*64);
        int wind = 0;
        float4 f0 = cvp[0];
        const float r0x = f0.x - plx, r0y = f0.y - ply;   // rel[0], saved for close
        float rpx = f0.z - plx, rpy = f0.w - ply;          // rel[1]
        float d2min = fminf(r0x*r0x + r0y*r0y, rpx*rpx + rpy*rpy);
        EDGE_STEP(r0x, r0y, rpx, rpy);                     // edge 0->1
        #pragma unroll 4
        for (int s2 = 1; s2 < 32; s2++) {
            float4 g = cvp[s2];
            float ax_ = g.x - plx, ay_ = g.y - ply;        // rel[2*s2]
            float bx_ = g.z - plx, by_ = g.w - ply;        // rel[2*s2+1]
            d2min = fminf(d2min, fminf(ax_*ax_ + ay_*ay_, bx_*bx_ + by_*by_));
            EDGE_STEP(rpx, rpy, ax_, ay_);
            EDGE_STEP(ax_, ay_, bx_, by_);
            rpx = bx_; rpy = by_;
        }
        EDGE_STEP(rpx, rpy, r0x, r0y);                     // closing edge 63->0

        const float dmin  = sqrtf(d2min + 1e-12f);
        const float sdf2d = (wind != 0) ? -dmin : dmin;
        const float dz = fabsf(plz) - h;
        const float e1 = fmaxf(sdf2d, 0.0f), e2 = fmaxf(dz, 0.0f);
        const float sdf = fminf(fmaxf(sdf2d, dz), 0.0f)
                        + sqrtf(e1*e1 + e2*e2 + 1e-12f);
        const float ex  = __expf(fminf(150.0f*sdf, 80.0f));
        const float occ = __fdividef(1.0f, 1.0f + ex);     // sigmoid(-150*sdf)
        sdf_s [k*33 + m_local] = sdf;
        dmin_s[k*33 + m_local] = dmin;
        occ_s [k*33 + m_local] = occ;
    }
    __syncthreads();

    // ---- Flush sdf / dmin coalesced: tile is (MTILE, KQ) m-major ----
    const int outbase = (b*MQ + m0) * KQ;
    for (int idx = tid; idx < MTILE*KQ; idx += NTHREADS) {
        const int mm = idx >> 6, kk = idx & 63;
        out[OUT_SDF + outbase + idx] = sdf_s [kk*33 + mm];
        out[OUT_SUP + outbase + idx] = dmin_s[kk*33 + mm];
    }
    __syncthreads();   // sdf_s about to be reused for inter

    // ---- Phase B: intersection layer. lane = m_local, warp-group handles 4 c ----
    const int training = flag ? *flag : 1;
    for (int j = 0; j < 4; j++) {
        const int c = ks*4 + j;
        float se = 0.0f, sp = 0.0f, mn = 3.0e38f;
        #pragma unroll 8
        for (int k = 0; k < KQ; k++) {
            float o  = occ_s[k*33 + m_local];        // conflict-free
            float wv = W_s[k*64 + c];                // warp-uniform broadcast
            float pre = fmaf(wv, o, 1.0f - wv);      // 1 - wv*(1-o)
            float e = __expf(-40.0f * pre);
            se += e;
            sp  = fmaf(e, pre, sp);
            mn  = fminf(mn, pre);
        }
        float inter = training ? __fdividef(sp, se) : mn;
        sdf_s[c*33 + m_local] = inter;               // reuse buffer
    }
    __syncthreads();

    for (int idx = tid; idx < MTILE*CQ; idx += NTHREADS) {
        const int mm = idx >> 6, cc = idx & 63;
        out[OUT_INTER + outbase + idx] = sdf_s[cc*33 + mm];
    }

    // ---- Phase C: union layer, one thread per point ----
    if (tid < MTILE) {
        const int mm = tid;
        float mx = -3.0e38f;
        #pragma unroll 8
        for (int c = 0; c < CQ; c++) {
            float v = u_s[c] * sdf_s[c*33 + mm];
            mx = fmaxf(mx, v);
        }
        float se = 0.0f, sp = 0.0f;
        #pragma unroll 8
        for (int c = 0; c < CQ; c++) {
            float v = u_s[c] * sdf_s[c*33 + mm];
            float e = __expf(40.0f * (v - mx));
            se += e;
            sp  = fmaf(e, v, sp);
        }
        out[OUT_OCC + b*MQ + m0 + mm] = training ? __fdividef(sp, se) : mx;
    }
}

extern "C" void kernel_launch(void* const* d_in, const int* in_sizes, int n_in,
                              void* d_out, int out_size) {
    const float* pts  = (const float*)d_in[0];
    const float* prim = (const float*)d_in[1];
    const float* Wg   = (const float*)d_in[2];
    const float* Ug   = (const float*)d_in[3];
    const int*   flag = (n_in >= 5) ? (const int*)d_in[4] : nullptr;
    float* out = (float*)d_out;

    const size_t smem = SMEM_FLOATS * sizeof(float);
    cudaFuncSetAttribute(extrude_kernel,
                         cudaFuncAttributeMaxDynamicSharedMemorySize, (int)smem);
    dim3 grid(MQ / MTILE, BQ);      // 64 x 4 = 256 blocks, 2 per SM
    extrude_kernel<<<grid, NTHREADS, smem>>>(pts, prim, Wg, Ug, flag, out);
}

// round 3
// speedup vs baseline: 1.3382x; 1.1490x over previous
#include <cuda_runtime.h>
#include <math.h>

// Problem constants
#define BQ 4
#define MQ 2048
#define KQ 64
#define CQ 64
#define SRQ 16
#define SQ 64          // NSEG * SAMPLE_RATE
#define PPQ 28         // params per primitive
#define MTILE 32
#define NTHREADS 512

// Output layout: occ (B,M) | sdf (B,M,K) | inter (B,M,C) | support (B,M,K)
#define OUT_OCC   0
#define OUT_SDF   (BQ*MQ)
#define OUT_INTER (OUT_SDF + BQ*MQ*KQ)
#define OUT_SUP   (OUT_INTER + BQ*MQ*CQ)

// Shared memory layout (float offsets) — W removed (read via warp-uniform LDG.128)
#define OFF_CURVE 0                       // 64k * 64s * float2 = 8192 floats
#define OFF_PRIM  (64*64*2)               // 8192 : 64*8
#define OFF_U     (OFF_PRIM + 512)        // 8704 : 64
#define OFF_OCC   (OFF_U + 64)            // 8768 : 64*33 (pitch 33)
#define OFF_SDF   (OFF_OCC + 64*33)       // 10880: 64*33 (reused for inter)
#define OFF_DMIN  (OFF_SDF + 64*33)       // 12992: 64*33
#define SMEM_FLOATS (OFF_DMIN + 64*33)    // 15104 floats = 60416 B -> 3 blocks/SM

// fast exp2
__device__ __forceinline__ float ex2f(float x) {
    float r;
    asm("ex2.approx.ftz.f32 %0, %1;" : "=f"(r) : "f"(x));
    return r;
}

// winding edge: carried predicate pp = (prev_y <= 0); rx,ry = prev rel
// +1 on up-crossing with cr>0, -1 on down-crossing with cr<0
#define EDGE(nx_, ny_)                                              \
    {                                                               \
        bool pn = (ny_) <= 0.0f;                                    \
        float cr = rx*(ny_) - ry*(nx_);                             \
        bool pc = cr > 0.0f;                                        \
        if ((pp != pn) && (pc != pn)) wind += pn ? -1 : 1;          \
        pp = pn; rx = (nx_); ry = (ny_);                            \
    }

__global__ __launch_bounds__(NTHREADS, 3)
void extrude_kernel(const float* __restrict__ pts,   // (B,M,3)
                    const float* __restrict__ prim,  // (B,28,K)
                    const float* __restrict__ Wg,    // (B,K,C)
                    const float* __restrict__ Ug,    // (B,C)
                    const int*   __restrict__ flag,  // is_training
                    float* __restrict__ out)
{
    extern __shared__ float sm[];
    float2* curve  = (float2*)(sm + OFF_CURVE);   // [k][s], pitch 64
    float*  prim_s = sm + OFF_PRIM;               // per-k: qw,qx,qy,qz,tx,ty,tz,|h|
    float*  u_s    = sm + OFF_U;
    float*  occ_s  = sm + OFF_OCC;
    float*  sdf_s  = sm + OFF_SDF;
    float*  dmin_s = sm + OFF_DMIN;

    const int tid = threadIdx.x;
    const int b   = blockIdx.y;
    const int m0  = blockIdx.x * MTILE;

    const float* P = prim + b * PPQ * KQ;

    // ---- Phase 0: per-b params + rational-bezier curve ----
    if (tid < KQ) {
        const int k = tid;
        float q0 = P[0*KQ+k], q1 = P[1*KQ+k], q2 = P[2*KQ+k], q3 = P[3*KQ+k];
        float inv = rsqrtf(q0*q0 + q1*q1 + q2*q2 + q3*q3 + 1e-8f);
        prim_s[k*8+0] =  q0*inv;
        prim_s[k*8+1] = -q1*inv;
        prim_s[k*8+2] = -q2*inv;
        prim_s[k*8+3] = -q3*inv;
        prim_s[k*8+4] = P[4*KQ+k];
        prim_s[k*8+5] = P[5*KQ+k];
        prim_s[k*8+6] = P[6*KQ+k];
        prim_s[k*8+7] = fabsf(P[7*KQ+k]);
    }
    if (tid >= KQ && tid < KQ + CQ) u_s[tid - KQ] = Ug[b*CQ + tid - KQ];

    if (tid < 256) {   // one (k, seg) per thread
        const int k   = tid >> 2;
        const int seg = tid & 3;
        const double PI = 3.14159265358979323846;
        const double thetaD = 2.0*PI/16.0 + atan(tan(2.0*PI/16.0)/3.0);
        const int sn = (seg + 1) & 3;
        const float a0  = (float)(PI/2.0 * seg);
        const float a1  = (float)(PI/2.0 * seg + thetaD);
        const float a2  = (float)(PI/2.0 * (seg+1) - thetaD);
        const float a0n = (float)(PI/2.0 * sn);
        const float r0 = fabsf(P[(8 + seg*3 + 0)*KQ + k]);
        const float r1 = fabsf(P[(8 + seg*3 + 1)*KQ + k]);
        const float r2 = fabsf(P[(8 + seg*3 + 2)*KQ + k]);
        const float rn = fabsf(P[(8 + sn*3  + 0)*KQ + k]);
        const float w1 = fabsf(P[(20 + seg*2 + 0)*KQ + k]);
        const float w2 = fabsf(P[(20 + seg*2 + 1)*KQ + k]);
        const float P0x = cosf(a0)*r0,  P0y = sinf(a0)*r0;
        const float P1x = cosf(a1)*r1,  P1y = sinf(a1)*r1;
        const float P2x = cosf(a2)*r2,  P2y = sinf(a2)*r2;
        const float P3x = cosf(a0n)*rn, P3y = sinf(a0n)*rn;
        float2* cv = curve + k*64 + seg*SRQ;
        #pragma unroll
        for (int j = 0; j < SRQ; j++) {
            float t  = j * (1.0f/SRQ);
            float u1 = 1.0f - t;
            float b0 = u1*u1*u1;
            float b1 = 3.0f*u1*u1*t;
            float b2 = 3.0f*u1*t*t;
            float b3 = t*t*t;
            float wb1 = w1*b1, wb2 = w2*b2;
            float invd = 1.0f / (b0 + wb1 + wb2 + b3);
            float x = (P0x*b0 + P1x*wb1 + P2x*wb2 + P3x*b3) * invd;
            float y = (P0y*b0 + P1y*wb1 + P2y*wb2 + P3y*b3) * invd;
            cv[j] = make_float2(x, y);
        }
    }
    __syncthreads();

    // ---- Phase A: per-(m,k) SDF. lane = m_local; warp ks handles 4 k ----
    const int m_local = tid & 31;
    const int ks      = tid >> 5;          // 0..15
    const int gm      = b*MQ + m0 + m_local;
    const float px = pts[gm*3+0], py = pts[gm*3+1], pz = pts[gm*3+2];

    for (int i = 0; i < 4; i++) {
        const int k = ks*4 + i;
        const float* pr = prim_s + k*8;    // warp-uniform broadcast
        const float qw = pr[0], qx = pr[1], qy = pr[2], qz = pr[3];
        const float ax = px - pr[4], ay = py - pr[5], az = pz - pr[6];
        const float h  = pr[7];
        const float t2x = 2.0f*(qy*az - qz*ay);
        const float t2y = 2.0f*(qz*ax - qx*az);
        const float t2z = 2.0f*(qx*ay - qy*ax);
        const float plx = ax + qw*t2x + (qy*t2z - qz*t2y);
        const float ply = ay + qw*t2y + (qz*t2x - qx*t2z);
        const float plz = az + qw*t2z + (qx*t2y - qy*t2x);

        const float4* cvp = (const float4*)(curve + k*64);
        int wind = 0;
        float4 f0 = cvp[0];
        const float r0x = f0.x - plx, r0y = f0.y - ply;
        float rx = r0x, ry = r0y;
        bool pp = (r0y <= 0.0f);
        float d2a = r0x*r0x + r0y*r0y;
        {
            float bx_ = f0.z - plx, by_ = f0.w - ply;
            d2a = fminf(d2a, bx_*bx_ + by_*by_);
            EDGE(bx_, by_);
        }
        float d2b = 3.0e38f;
        #pragma unroll 8
        for (int s2 = 1; s2 < 32; s2++) {
            float4 g = cvp[s2];
            float ax_ = g.x - plx, ay_ = g.y - ply;
            d2a = fminf(d2a, ax_*ax_ + ay_*ay_);
            EDGE(ax_, ay_);
            float bx_ = g.z - plx, by_ = g.w - ply;
            d2b = fminf(d2b, bx_*bx_ + by_*by_);
            EDGE(bx_, by_);
        }
        EDGE(r0x, r0y);                     // closing edge 63->0
        const float d2min = fminf(d2a, d2b);

        const float dmin  = sqrtf(d2min + 1e-12f);
        const float sdf2d = (wind != 0) ? -dmin : dmin;
        const float dz = fabsf(plz) - h;
        const float e1 = fmaxf(sdf2d, 0.0f), e2 = fmaxf(dz, 0.0f);
        const float sdf = fminf(fmaxf(sdf2d, dz), 0.0f)
                        + sqrtf(e1*e1 + e2*e2 + 1e-12f);
        const float ex  = ex2f(fminf(216.404256f * sdf, 126.0f)); // exp(150*sdf)
        const float occ = __fdividef(1.0f, 1.0f + ex);            // sigmoid(-150*sdf)
        sdf_s [k*33 + m_local] = sdf;
        dmin_s[k*33 + m_local] = dmin;
        occ_s [k*33 + m_local] = occ;
    }
    __syncthreads();

    // ---- Flush sdf / dmin coalesced ----
    const int outbase = (b*MQ + m0) * KQ;
    for (int idx = tid; idx < MTILE*KQ; idx += NTHREADS) {
        const int mm = idx >> 6, kk = idx & 63;
        out[OUT_SDF + outbase + idx] = sdf_s [kk*33 + mm];
        out[OUT_SUP + outbase + idx] = dmin_s[kk*33 + mm];
    }
    __syncthreads();   // sdf_s reused for inter

    // ---- Phase B: intersection layer. warp ks handles c = ks*4 .. ks*4+3 ----
    const int training = flag ? *flag : 1;
    const float* Wrow = Wg + b*KQ*CQ + ks*4;   // warp-uniform
    if (training) {
        float se0 = 0.f, se1 = 0.f, se2 = 0.f, se3 = 0.f;
        float sp0 = 0.f, sp1 = 0.f, sp2 = 0.f, sp3 = 0.f;
        #pragma unroll 4
        for (int k = 0; k < KQ; k++) {
            float o  = occ_s[k*33 + m_local];
            float4 wv = *(const float4*)(Wrow + k*CQ);   // LDG.128 broadcast
            float om = 1.0f - o;
            float t  = 57.707801f * om;                  // 40*log2(e)*(1-o)
            // e = exp(-40*pre) * exp(40) = exp2(wv*t)  (constant cancels in ratio)
            float e0 = ex2f(wv.x * t), p0 = fmaf(-wv.x, om, 1.0f);
            float e1 = ex2f(wv.y * t), p1 = fmaf(-wv.y, om, 1.0f);
            float e2 = ex2f(wv.z * t), p2 = fmaf(-wv.z, om, 1.0f);
            float e3 = ex2f(wv.w * t), p3 = fmaf(-wv.w, om, 1.0f);
            se0 += e0; sp0 = fmaf(e0, p0, sp0);
            se1 += e1; sp1 = fmaf(e1, p1, sp1);
            se2 += e2; sp2 = fmaf(e2, p2, sp2);
            se3 += e3; sp3 = fmaf(e3, p3, sp3);
        }
        sdf_s[(ks*4+0)*33 + m_local] = __fdividef(sp0, se0);
        sdf_s[(ks*4+1)*33 + m_local] = __fdividef(sp1, se1);
        sdf_s[(ks*4+2)*33 + m_local] = __fdividef(sp2, se2);
        sdf_s[(ks*4+3)*33 + m_local] = __fdividef(sp3, se3);
    } else {
        float mn0 = 3.0e38f, mn1 = 3.0e38f, mn2 = 3.0e38f, mn3 = 3.0e38f;
        #pragma unroll 4
        for (int k = 0; k < KQ; k++) {
            float o  = occ_s[k*33 + m_local];
            float4 wv = *(const float4*)(Wrow + k*CQ);
            float om = 1.0f - o;
            mn0 = fminf(mn0, fmaf(-wv.x, om, 1.0f));
            mn1 = fminf(mn1, fmaf(-wv.y, om, 1.0f));
            mn2 = fminf(mn2, fmaf(-wv.z, om, 1.0f));
            mn3 = fminf(mn3, fmaf(-wv.w, om, 1.0f));
        }
        sdf_s[(ks*4+0)*33 + m_local] = mn0;
        sdf_s[(ks*4+1)*33 + m_local] = mn1;
        sdf_s[(ks*4+2)*33 + m_local] = mn2;
        sdf_s[(ks*4+3)*33 + m_local] = mn3;
    }
    __syncthreads();

    for (int idx = tid; idx < MTILE*CQ; idx += NTHREADS) {
        const int mm = idx >> 6, cc = idx & 63;
        out[OUT_INTER + outbase + idx] = sdf_s[cc*33 + mm];
    }

    // ---- Phase C: union layer, one thread per point ----
    if (tid < MTILE) {
        const int mm = tid;
        float mx = -3.0e38f;
        #pragma unroll 8
        for (int c = 0; c < CQ; c++) {
            float v = u_s[c] * sdf_s[c*33 + mm];
            mx = fmaxf(mx, v);
        }
        float se = 0.0f, sp = 0.0f;
        #pragma unroll 8
        for (int c = 0; c < CQ; c++) {
            float v = u_s[c] * sdf_s[c*33 + mm];
            float e = ex2f(57.707801f * (v - mx));   // exp(40*(v-mx))
            se += e;
            sp  = fmaf(e, v, sp);
        }
        out[OUT_OCC + b*MQ + m0 + mm] = (flag ? *flag : 1) ? __fdividef(sp, se) : mx;
    }
}

extern "C" void kernel_launch(void* const* d_in, const int* in_sizes, int n_in,
                              void* d_out, int out_size) {
    const float* pts  = (const float*)d_in[0];
    const float* prim = (const float*)d_in[1];
    const float* Wg   = (const float*)d_in[2];
    const float* Ug   = (const float*)d_in[3];
    const int*   flag = (n_in >= 5) ? (const int*)d_in[4] : nullptr;
    float* out = (float*)d_out;

    const size_t smem = SMEM_FLOATS * sizeof(float);
    cudaFuncSetAttribute(extrude_kernel,
                         cudaFuncAttributeMaxDynamicSharedMemorySize, (int)smem);
    dim3 grid(MQ / MTILE, BQ);      // 64 x 4 = 256 blocks, 3 per SM capacity
    extrude_kernel<<<grid, NTHREADS, smem>>>(pts, prim, Wg, Ug, flag, out);
}